// round 11
// baseline (speedup 1.0000x reference)
#include <cuda_runtime.h>
#include <cuda_fp16.h>
#include <cstdint>

#define T_LEN 512
#define B_SZ  2048
#define BP    1024                 // batch pairs
#define HID   23
#define G3    69                   // 3*H
#define FIN   32
#define D2    46                   // 2*H
#define OUTD  8
#define M_PAIRS ((size_t)T_LEN * BP)   // 524288 row-pairs

// ---------------- scratch (device globals; no allocation) ----------------
// pair-packed half2: .x = batch 2p, .y = batch 2p+1
__device__ __align__(16) __half2 g_xg2h[2 * M_PAIRS * G3];   // 290 MB
__device__ __align__(16) __half2 g_sA2h[M_PAIRS * D2];       // 96.5 MB
__device__ __align__(16) __half2 g_sB2h[M_PAIRS * D2];

__device__ __forceinline__ float2 ffma2(float2 a, float2 b, float2 c) {
    union U { float2 f; unsigned long long u; };
    U ua, ub, uc, ud;
    ua.f = a; ub.f = b; uc.f = c;
    asm("fma.rn.f32x2 %0, %1, %2, %3;"
        : "=l"(ud.u) : "l"(ua.u), "l"(ub.u), "l"(uc.u));
    return ud.f;
}

__device__ __forceinline__ float tanhx(float x) {
    float y;
    asm("tanh.approx.f32 %0, %1;" : "=f"(y) : "f"(x));
    return y;
}

// ---------------- input-gate GEMM via mma.sync (fp16 in, fp32 accum) -----------
// CTA = 128 thr = 4 warps. Tile: 64 rows (batch) x 72 cols (gates) x AK (K pad 16).
// Warp w owns rows [16w, 16w+16). m16n8k16: 9 n-frags, KF k-frags.
// A staged de-interleaved in smem [64][AKP]; B (weights) [72][AKP] fp16.
// Epilogue restages pair-packed half2 and copies out contiguous uint4.
template <int K>
__global__ __launch_bounds__(128)
void xg_mma(int insel, const float* __restrict__ w_ih, const float* __restrict__ b_ih,
            const float* __restrict__ xin, const float* __restrict__ fmean,
            const float* __restrict__ fstd) {
    constexpr int AK  = (K + 15) / 16 * 16;   // 32 or 48
    constexpr int KF  = AK / 16;              // 2 or 3
    constexpr int AKP = AK + 2;               // conflict-free padded stride (even)

    __shared__ __align__(16) char smem_raw[136 * AKP * 2];   // As + Bs (>= 8832 staging)
    __shared__ float biass[72];
    __shared__ float fm_s[FIN], fi_s[FIN];

    __half* As = (__half*)smem_raw;            // [64][AKP]
    __half* Bs = As + 64 * AKP;                // [72][AKP]

    const int d   = blockIdx.y;
    const int bx  = blockIdx.x;
    const int tid = threadIdx.x;
    const float* W = w_ih + (size_t)d * G3 * K;
    const size_t pbase = (size_t)bx * 32;      // global pair index base

    // weights -> smem fp16 (zero-padded)
    for (int idx = tid; idx < 72 * AK; idx += 128) {
        int n = idx / AK, kk = idx % AK;
        float wv = (n < G3 && kk < K) ? W[n * K + kk] : 0.0f;
        Bs[n * AKP + kk] = __float2half_rn(wv);
    }
    if (tid < 72) biass[tid] = (tid < G3) ? b_ih[d * G3 + tid] : 0.0f;
    if (insel == 0 && tid < FIN) {
        float s = fstd[tid];
        float adj = (s == 0.0f) ? 1.0f : s;
        bool zero = (adj == 1.0f);
        fi_s[tid] = zero ? 0.0f : __fdividef(1.0f, adj);
        fm_s[tid] = zero ? 0.0f : fmean[tid];
    }
    __syncthreads();

    // A tile -> smem, de-interleaved [row][k]
    if (insel == 0) {
        int t  = bx >> 5;              // 32 blocks per timestep (BP/32)
        int b0 = (bx & 31) * 64;
        for (int idx = tid; idx < 64 * 8; idx += 128) {
            int row = idx >> 3, q = idx & 7;
            float4 v4 = *(const float4*)(xin + ((size_t)(b0 + row) * T_LEN + t) * FIN + q * 4);
            int k0 = q * 4;
            __half2 h01 = __floats2half2_rn((v4.x - fm_s[k0 + 0]) * fi_s[k0 + 0],
                                            (v4.y - fm_s[k0 + 1]) * fi_s[k0 + 1]);
            __half2 h23 = __floats2half2_rn((v4.z - fm_s[k0 + 2]) * fi_s[k0 + 2],
                                            (v4.w - fm_s[k0 + 3]) * fi_s[k0 + 3]);
            *(__half2*)&As[row * AKP + k0]     = h01;
            *(__half2*)&As[row * AKP + k0 + 2] = h23;
        }
    } else {
        const __half2* in2 = (insel == 1) ? g_sA2h : g_sB2h;
        for (int idx = tid; idx < 32 * AK; idx += 128) {
            int p = idx / AK, kk = idx % AK;
            __half2 v = (kk < K) ? in2[(pbase + p) * K + kk]
                                 : __floats2half2_rn(0.0f, 0.0f);
            As[(2 * p) * AKP + kk]     = __low2half(v);
            As[(2 * p + 1) * AKP + kk] = __high2half(v);
        }
    }
    __syncthreads();

    const int warp = tid >> 5;
    const int lane = tid & 31;
    const int g   = lane >> 2;     // 0..7
    const int tig = lane & 3;      // 0..3
    const int rowA = warp * 16 + g;

    // accumulators init with bias
    float acc[9][4];
#pragma unroll
    for (int nf = 0; nf < 9; nf++) {
        int c0 = nf * 8 + 2 * tig;
        float b0v = biass[c0], b1v = biass[c0 + 1];
        acc[nf][0] = b0v; acc[nf][1] = b1v;
        acc[nf][2] = b0v; acc[nf][3] = b1v;
    }

#pragma unroll
    for (int kf = 0; kf < KF; kf++) {
        int k0 = kf * 16;
        uint32_t a0 = *(const uint32_t*)&As[(rowA)     * AKP + k0 + 2 * tig];
        uint32_t a1 = *(const uint32_t*)&As[(rowA + 8) * AKP + k0 + 2 * tig];
        uint32_t a2 = *(const uint32_t*)&As[(rowA)     * AKP + k0 + 2 * tig + 8];
        uint32_t a3 = *(const uint32_t*)&As[(rowA + 8) * AKP + k0 + 2 * tig + 8];
#pragma unroll
        for (int nf = 0; nf < 9; nf++) {
            int nB = nf * 8 + g;
            uint32_t b0 = *(const uint32_t*)&Bs[nB * AKP + k0 + 2 * tig];
            uint32_t b1 = *(const uint32_t*)&Bs[nB * AKP + k0 + 2 * tig + 8];
            asm("mma.sync.aligned.m16n8k16.row.col.f32.f16.f16.f32 "
                "{%0,%1,%2,%3}, {%4,%5,%6,%7}, {%8,%9}, {%0,%1,%2,%3};"
                : "+f"(acc[nf][0]), "+f"(acc[nf][1]), "+f"(acc[nf][2]), "+f"(acc[nf][3])
                : "r"(a0), "r"(a1), "r"(a2), "r"(a3), "r"(b0), "r"(b1));
        }
    }

    // restage pair-packed fp16 and copy out
    __syncthreads();
    __half* st = (__half*)smem_raw;   // [32 pairs][69] as half pairs
    const int p0 = rowA >> 1, comp = rowA & 1;
    const int p1 = (rowA + 8) >> 1;   // same parity
#pragma unroll
    for (int nf = 0; nf < 9; nf++) {
        int c0 = nf * 8 + 2 * tig;
        int c1 = c0 + 1;
        if (c0 < G3) {
            st[(p0 * G3 + c0) * 2 + comp] = __float2half_rn(acc[nf][0]);
            st[(p1 * G3 + c0) * 2 + comp] = __float2half_rn(acc[nf][2]);
        }
        if (c1 < G3) {
            st[(p0 * G3 + c1) * 2 + comp] = __float2half_rn(acc[nf][1]);
            st[(p1 * G3 + c1) * 2 + comp] = __float2half_rn(acc[nf][3]);
        }
    }
    __syncthreads();

    uint4* dst = (uint4*)(g_xg2h + ((size_t)d * M_PAIRS + pbase) * G3);
    const uint4* src = (const uint4*)st;
    const int n16 = 32 * G3 * 4 / 16;   // 552
    for (int i = tid; i < n16; i += 128) dst[i] = src[i];
}

// ---------------- GRU recurrence (f32x2): one warp per (batch pair, dir) ----------------
__global__ __launch_bounds__(64)
void gru_kernel(const float* __restrict__ w_hh, const float* __restrict__ b_hh, int outsel) {
    const int d = blockIdx.y;
    const int warp = threadIdx.x >> 5;
    const int lane = threadIdx.x & 31;
    const int bp = blockIdx.x * 2 + warp;
    __half2* seq2 = (outsel == 1) ? g_sA2h : g_sB2h;

    __shared__ float2 hs[2][2][HID + 1];   // [warp][parity][unit]

    const float* W  = w_hh + (size_t)d * G3 * HID;
    const float* bh = b_hh + d * G3;

    const int j = lane;
    const bool active = (j < HID);
    const int jj = active ? j : 0;

    float2 wr2[HID], wz2[HID], wn2[HID];
#pragma unroll
    for (int k = 0; k < HID; k++) {
        float wr = W[(jj) * HID + k];
        float wz = W[(jj + HID) * HID + k];
        float wn = W[(jj + 2 * HID) * HID + k];
        wr2[k] = make_float2(wr, wr);
        wz2[k] = make_float2(wz, wz);
        wn2[k] = make_float2(wn, wn);
    }
    float brv = bh[jj], bzv = bh[jj + HID], bnv = bh[jj + 2 * HID];
    float2 br2 = make_float2(brv, brv);
    float2 bz2 = make_float2(bzv, bzv);
    float2 bn2 = make_float2(bnv, bnv);

    if (active) hs[warp][0][j] = make_float2(0.0f, 0.0f);
    float2 h = make_float2(0.0f, 0.0f);
    __syncwarp();

    const __half2* xgd = g_xg2h + (size_t)d * M_PAIRS * G3;
    const int t0 = (d == 0) ? 0 : (T_LEN - 1);
    const int dt = (d == 0) ? 1 : -1;

    __half2 xr_n, xz_n, xn_n;
    {
        size_t row0 = ((size_t)t0 * BP + bp) * G3;
        xr_n = xgd[row0 + jj];
        xz_n = xgd[row0 + jj + HID];
        xn_n = xgd[row0 + jj + 2 * HID];
    }

    int par = 0;
    for (int s = 0; s < T_LEN; s++) {
        const int t = t0 + s * dt;
        float2 xr = __half22float2(xr_n);
        float2 xz = __half22float2(xz_n);
        float2 xn = __half22float2(xn_n);
        if (s + 1 < T_LEN) {
            size_t rown = ((size_t)(t + dt) * BP + bp) * G3;
            xr_n = xgd[rown + jj];
            xz_n = xgd[rown + jj + HID];
            xn_n = xgd[rown + jj + 2 * HID];
        }
        float2 ar = br2, az = bz2, an = bn2;
        const float2* hrow = hs[warp][par];
#pragma unroll
        for (int k = 0; k < HID; k++) {
            float2 hk = hrow[k];
            ar = ffma2(hk, wr2[k], ar);
            az = ffma2(hk, wz2[k], az);
            an = ffma2(hk, wn2[k], an);
        }
        // sigmoid(x) = 0.5 + 0.5*tanh(0.5x); HW tanh.approx
        float rX = fmaf(0.5f, tanhx(0.5f * (xr.x + ar.x)), 0.5f);
        float rY = fmaf(0.5f, tanhx(0.5f * (xr.y + ar.y)), 0.5f);
        float zX = fmaf(0.5f, tanhx(0.5f * (xz.x + az.x)), 0.5f);
        float zY = fmaf(0.5f, tanhx(0.5f * (xz.y + az.y)), 0.5f);
        float nX = tanhx(fmaf(rX, an.x, xn.x));
        float nY = tanhx(fmaf(rY, an.y, xn.y));
        h.x = fmaf(zX, h.x - nX, nX);
        h.y = fmaf(zY, h.y - nY, nY);

        if (active) hs[warp][par ^ 1][j] = h;
        __syncwarp();
        par ^= 1;
        if (active) seq2[((size_t)t * BP + bp) * D2 + d * HID + j] = __float22half2_rn(h);
    }
}

// ---------------- FC epilogue on last timestep ----------------
__global__ void fc_kernel(const float* __restrict__ fc_w, const float* __restrict__ fc_b,
                          const float* __restrict__ omean, const float* __restrict__ ostd,
                          float* __restrict__ out) {
    int idx = blockIdx.x * blockDim.x + threadIdx.x;
    if (idx >= B_SZ * OUTD) return;
    int b = idx / OUTD, o = idx % OUTD;
    const __half2* lastp = g_sA2h + ((size_t)(T_LEN - 1) * BP + (b >> 1)) * D2;
    int par = b & 1;
    float acc = fc_b[o];
#pragma unroll
    for (int k = 0; k < D2; k++) {
        float2 v = __half22float2(lastp[k]);
        float hv = par ? v.y : v.x;
        acc += hv * fc_w[o * D2 + k];
    }
    out[idx] = acc * ostd[o] + omean[o];
}

// ---------------- launch ----------------
extern "C" void kernel_launch(void* const* d_in, const int* in_sizes, int n_in,
                              void* d_out, int out_size) {
    const float* x         = (const float*)d_in[0];
    const float* fmean     = (const float*)d_in[1];
    const float* fstd      = (const float*)d_in[2];
    const float* omean     = (const float*)d_in[3];
    const float* ostd      = (const float*)d_in[4];
    const float* w_ih_l0   = (const float*)d_in[5];
    const float* w_hh_l0   = (const float*)d_in[6];
    const float* b_ih_l0   = (const float*)d_in[7];
    const float* b_hh_l0   = (const float*)d_in[8];
    const float* w_ih_rest = (const float*)d_in[9];
    const float* w_hh_rest = (const float*)d_in[10];
    const float* b_ih_rest = (const float*)d_in[11];
    const float* b_hh_rest = (const float*)d_in[12];
    const float* fc_w      = (const float*)d_in[13];
    const float* fc_b      = (const float*)d_in[14];
    float* out             = (float*)d_out;

    dim3 xg_grid((unsigned)(M_PAIRS / 32), 2);   // 16384 x 2
    dim3 gru_grid(BP / 2, 2);

    // layer 0: x (fused norm) -> sA2
    xg_mma<FIN><<<xg_grid, 128>>>(0, w_ih_l0, b_ih_l0, x, fmean, fstd);
    gru_kernel<<<gru_grid, 64>>>(w_hh_l0, b_hh_l0, /*outsel=*/1);

    // layer 1: sA2 -> sB2
    xg_mma<D2><<<xg_grid, 128>>>(1, w_ih_rest, b_ih_rest, nullptr, nullptr, nullptr);
    gru_kernel<<<gru_grid, 64>>>(w_hh_rest, b_hh_rest, /*outsel=*/2);

    // layer 2: sB2 -> sA2
    xg_mma<D2><<<xg_grid, 128>>>(2, w_ih_rest + (size_t)2 * G3 * D2,
                                 b_ih_rest + 2 * G3, nullptr, nullptr, nullptr);
    gru_kernel<<<gru_grid, 64>>>(w_hh_rest + (size_t)2 * G3 * HID,
                                 b_hh_rest + 2 * G3, /*outsel=*/1);

    // FC epilogue
    {
        int threads = 256;
        int blocks = (B_SZ * OUTD + threads - 1) / threads;
        fc_kernel<<<blocks, threads>>>(fc_w, fc_b, omean, ostd, out);
    }
}

// round 12
// speedup vs baseline: 1.6449x; 1.6449x over previous
#include <cuda_runtime.h>
#include <cuda_fp16.h>
#include <cstdint>

#define T_LEN 512
#define B_SZ  2048
#define BP    1024                 // batch pairs
#define HID   23
#define G3    69                   // 3*H
#define FIN   32
#define D2    46                   // 2*H
#define OUTD  8
#define M_PAIRS ((size_t)T_LEN * BP)   // 524288 row-pairs

// ---------------- scratch (device globals; no allocation) ----------------
// pair-packed half2: .x = batch 2p, .y = batch 2p+1
__device__ __align__(16) __half2 g_xg2h[2 * M_PAIRS * G3];   // 290 MB
__device__ __align__(16) __half2 g_sA2h[M_PAIRS * D2];       // 96.5 MB
__device__ __align__(16) __half2 g_sB2h[M_PAIRS * D2];

__device__ __forceinline__ float2 ffma2(float2 a, float2 b, float2 c) {
    union U { float2 f; unsigned long long u; };
    U ua, ub, uc, ud;
    ua.f = a; ub.f = b; uc.f = c;
    asm("fma.rn.f32x2 %0, %1, %2, %3;"
        : "=l"(ud.u) : "l"(ua.u), "l"(ub.u), "l"(uc.u));
    return ud.f;
}

__device__ __forceinline__ float2 fadd2(float2 a, float2 b) {
    union U { float2 f; unsigned long long u; };
    U ua, ub, uc;
    ua.f = a; ub.f = b;
    asm("add.rn.f32x2 %0, %1, %2;" : "=l"(uc.u) : "l"(ua.u), "l"(ub.u));
    return uc.f;
}

__device__ __forceinline__ float tanhx(float x) {
    float y;
    asm("tanh.approx.f32 %0, %1;" : "=f"(y) : "f"(x));
    return y;
}

// ---------------- input-gate GEMM via mma.sync (fp16 in, fp32 accum) -----------
// CTA = 128 thr = 4 warps. Tile: 64 rows (batch) x 72 cols (gates) x AK (K pad 16).
template <int K>
__global__ __launch_bounds__(128)
void xg_mma(int insel, const float* __restrict__ w_ih, const float* __restrict__ b_ih,
            const float* __restrict__ xin, const float* __restrict__ fmean,
            const float* __restrict__ fstd) {
    constexpr int AK  = (K + 15) / 16 * 16;   // 32 or 48
    constexpr int KF  = AK / 16;              // 2 or 3
    constexpr int AKP = AK + 2;               // conflict-free padded stride (even)

    __shared__ __align__(16) char smem_raw[136 * AKP * 2];   // As + Bs (>= 8832 staging)
    __shared__ float biass[72];
    __shared__ float fm_s[FIN], fi_s[FIN];

    __half* As = (__half*)smem_raw;            // [64][AKP]
    __half* Bs = As + 64 * AKP;                // [72][AKP]

    const int d   = blockIdx.y;
    const int bx  = blockIdx.x;
    const int tid = threadIdx.x;
    const float* W = w_ih + (size_t)d * G3 * K;
    const size_t pbase = (size_t)bx * 32;      // global pair index base

    // weights -> smem fp16 (zero-padded)
    for (int idx = tid; idx < 72 * AK; idx += 128) {
        int n = idx / AK, kk = idx % AK;
        float wv = (n < G3 && kk < K) ? W[n * K + kk] : 0.0f;
        Bs[n * AKP + kk] = __float2half_rn(wv);
    }
    if (tid < 72) biass[tid] = (tid < G3) ? b_ih[d * G3 + tid] : 0.0f;
    if (insel == 0 && tid < FIN) {
        float s = fstd[tid];
        float adj = (s == 0.0f) ? 1.0f : s;
        bool zero = (adj == 1.0f);
        fi_s[tid] = zero ? 0.0f : __fdividef(1.0f, adj);
        fm_s[tid] = zero ? 0.0f : fmean[tid];
    }
    __syncthreads();

    // A tile -> smem, de-interleaved [row][k]
    if (insel == 0) {
        int t  = bx >> 5;              // 32 blocks per timestep (BP/32)
        int b0 = (bx & 31) * 64;
        for (int idx = tid; idx < 64 * 8; idx += 128) {
            int row = idx >> 3, q = idx & 7;
            float4 v4 = *(const float4*)(xin + ((size_t)(b0 + row) * T_LEN + t) * FIN + q * 4);
            int k0 = q * 4;
            __half2 h01 = __floats2half2_rn((v4.x - fm_s[k0 + 0]) * fi_s[k0 + 0],
                                            (v4.y - fm_s[k0 + 1]) * fi_s[k0 + 1]);
            __half2 h23 = __floats2half2_rn((v4.z - fm_s[k0 + 2]) * fi_s[k0 + 2],
                                            (v4.w - fm_s[k0 + 3]) * fi_s[k0 + 3]);
            *(__half2*)&As[row * AKP + k0]     = h01;
            *(__half2*)&As[row * AKP + k0 + 2] = h23;
        }
    } else {
        const __half2* in2 = (insel == 1) ? g_sA2h : g_sB2h;
        for (int idx = tid; idx < 32 * AK; idx += 128) {
            int p = idx / AK, kk = idx % AK;
            __half2 v = (kk < K) ? in2[(pbase + p) * K + kk]
                                 : __floats2half2_rn(0.0f, 0.0f);
            As[(2 * p) * AKP + kk]     = __low2half(v);
            As[(2 * p + 1) * AKP + kk] = __high2half(v);
        }
    }
    __syncthreads();

    const int warp = tid >> 5;
    const int lane = tid & 31;
    const int g   = lane >> 2;     // 0..7
    const int tig = lane & 3;      // 0..3
    const int rowA = warp * 16 + g;

    // accumulators init with bias
    float acc[9][4];
#pragma unroll
    for (int nf = 0; nf < 9; nf++) {
        int c0 = nf * 8 + 2 * tig;
        float b0v = biass[c0], b1v = biass[c0 + 1];
        acc[nf][0] = b0v; acc[nf][1] = b1v;
        acc[nf][2] = b0v; acc[nf][3] = b1v;
    }

#pragma unroll
    for (int kf = 0; kf < KF; kf++) {
        int k0 = kf * 16;
        uint32_t a0 = *(const uint32_t*)&As[(rowA)     * AKP + k0 + 2 * tig];
        uint32_t a1 = *(const uint32_t*)&As[(rowA + 8) * AKP + k0 + 2 * tig];
        uint32_t a2 = *(const uint32_t*)&As[(rowA)     * AKP + k0 + 2 * tig + 8];
        uint32_t a3 = *(const uint32_t*)&As[(rowA + 8) * AKP + k0 + 2 * tig + 8];
#pragma unroll
        for (int nf = 0; nf < 9; nf++) {
            int nB = nf * 8 + g;
            uint32_t b0 = *(const uint32_t*)&Bs[nB * AKP + k0 + 2 * tig];
            uint32_t b1 = *(const uint32_t*)&Bs[nB * AKP + k0 + 2 * tig + 8];
            asm("mma.sync.aligned.m16n8k16.row.col.f32.f16.f16.f32 "
                "{%0,%1,%2,%3}, {%4,%5,%6,%7}, {%8,%9}, {%0,%1,%2,%3};"
                : "+f"(acc[nf][0]), "+f"(acc[nf][1]), "+f"(acc[nf][2]), "+f"(acc[nf][3])
                : "r"(a0), "r"(a1), "r"(a2), "r"(a3), "r"(b0), "r"(b1));
        }
    }

    // restage pair-packed fp16 and copy out
    __syncthreads();
    __half* st = (__half*)smem_raw;   // [32 pairs][69] as half pairs
    const int p0 = rowA >> 1, comp = rowA & 1;
    const int p1 = (rowA + 8) >> 1;   // same parity
#pragma unroll
    for (int nf = 0; nf < 9; nf++) {
        int c0 = nf * 8 + 2 * tig;
        int c1 = c0 + 1;
        if (c0 < G3) {
            st[(p0 * G3 + c0) * 2 + comp] = __float2half_rn(acc[nf][0]);
            st[(p1 * G3 + c0) * 2 + comp] = __float2half_rn(acc[nf][2]);
        }
        if (c1 < G3) {
            st[(p0 * G3 + c1) * 2 + comp] = __float2half_rn(acc[nf][1]);
            st[(p1 * G3 + c1) * 2 + comp] = __float2half_rn(acc[nf][3]);
        }
    }
    __syncthreads();

    uint4* dst = (uint4*)(g_xg2h + ((size_t)d * M_PAIRS + pbase) * G3);
    const uint4* src = (const uint4*)st;
    const int n16 = 32 * G3 * 4 / 16;   // 552
    for (int i = tid; i < n16; i += 128) dst[i] = src[i];
}

// ---------------- GRU recurrence (f32x2): one warp per (batch pair, dir) ----------------
// Prefetch depth 4 on xg loads; gate matvec chains split even/odd for latency.
#define PF 4

__global__ __launch_bounds__(64)
void gru_kernel(const float* __restrict__ w_hh, const float* __restrict__ b_hh, int outsel) {
    const int d = blockIdx.y;
    const int warp = threadIdx.x >> 5;
    const int lane = threadIdx.x & 31;
    const int bp = blockIdx.x * 2 + warp;
    __half2* seq2 = (outsel == 1) ? g_sA2h : g_sB2h;

    __shared__ float2 hs[2][2][HID + 1];   // [warp][parity][unit]

    const float* W  = w_hh + (size_t)d * G3 * HID;
    const float* bh = b_hh + d * G3;

    const int j = lane;
    const bool active = (j < HID);
    const int jj = active ? j : 0;

    float2 wr2[HID], wz2[HID], wn2[HID];
#pragma unroll
    for (int k = 0; k < HID; k++) {
        float wr = W[(jj) * HID + k];
        float wz = W[(jj + HID) * HID + k];
        float wn = W[(jj + 2 * HID) * HID + k];
        wr2[k] = make_float2(wr, wr);
        wz2[k] = make_float2(wz, wz);
        wn2[k] = make_float2(wn, wn);
    }
    float brv = bh[jj], bzv = bh[jj + HID], bnv = bh[jj + 2 * HID];
    float2 br2 = make_float2(brv, brv);
    float2 bz2 = make_float2(bzv, bzv);
    float2 bn2 = make_float2(bnv, bnv);

    if (active) hs[warp][0][j] = make_float2(0.0f, 0.0f);
    float2 h = make_float2(0.0f, 0.0f);
    __syncwarp();

    const __half2* xgd = g_xg2h + (size_t)d * M_PAIRS * G3;
    const int t0 = (d == 0) ? 0 : (T_LEN - 1);
    const int dt = (d == 0) ? 1 : -1;

    // deep prefetch ring (registers; indices constant under unroll-by-4)
    __half2 pxr[PF], pxz[PF], pxn[PF];
#pragma unroll
    for (int q = 0; q < PF; q++) {
        size_t row = ((size_t)(t0 + q * dt) * BP + bp) * G3;
        pxr[q] = xgd[row + jj];
        pxz[q] = xgd[row + jj + HID];
        pxn[q] = xgd[row + jj + 2 * HID];
    }

    int par = 0;
#pragma unroll 4
    for (int s = 0; s < T_LEN; s++) {
        const int q = s & (PF - 1);
        float2 xr = __half22float2(pxr[q]);
        float2 xz = __half22float2(pxz[q]);
        float2 xn = __half22float2(pxn[q]);
        if (s + PF < T_LEN) {
            size_t rown = ((size_t)(t0 + (s + PF) * dt) * BP + bp) * G3;
            pxr[q] = xgd[rown + jj];
            pxz[q] = xgd[rown + jj + HID];
            pxn[q] = xgd[rown + jj + 2 * HID];
        }

        const float2* hrow = hs[warp][par];
        float2 ar0 = br2, az0 = bz2, an0 = bn2;
        float2 ar1 = make_float2(0.0f, 0.0f);
        float2 az1 = make_float2(0.0f, 0.0f);
        float2 an1 = make_float2(0.0f, 0.0f);
#pragma unroll
        for (int k = 0; k < HID - 1; k += 2) {
            float2 h0 = hrow[k];
            float2 h1 = hrow[k + 1];
            ar0 = ffma2(h0, wr2[k], ar0);
            az0 = ffma2(h0, wz2[k], az0);
            an0 = ffma2(h0, wn2[k], an0);
            ar1 = ffma2(h1, wr2[k + 1], ar1);
            az1 = ffma2(h1, wz2[k + 1], az1);
            an1 = ffma2(h1, wn2[k + 1], an1);
        }
        {
            float2 hl = hrow[HID - 1];
            ar0 = ffma2(hl, wr2[HID - 1], ar0);
            az0 = ffma2(hl, wz2[HID - 1], az0);
            an0 = ffma2(hl, wn2[HID - 1], an0);
        }
        float2 ar = fadd2(ar0, ar1);
        float2 az = fadd2(az0, az1);
        float2 an = fadd2(an0, an1);

        // sigmoid(x) = 0.5 + 0.5*tanh(0.5x); HW tanh.approx
        float rX = fmaf(0.5f, tanhx(0.5f * (xr.x + ar.x)), 0.5f);
        float rY = fmaf(0.5f, tanhx(0.5f * (xr.y + ar.y)), 0.5f);
        float zX = fmaf(0.5f, tanhx(0.5f * (xz.x + az.x)), 0.5f);
        float zY = fmaf(0.5f, tanhx(0.5f * (xz.y + az.y)), 0.5f);
        float nX = tanhx(fmaf(rX, an.x, xn.x));
        float nY = tanhx(fmaf(rY, an.y, xn.y));
        h.x = fmaf(zX, h.x - nX, nX);
        h.y = fmaf(zY, h.y - nY, nY);

        if (active) hs[warp][par ^ 1][j] = h;
        __syncwarp();
        par ^= 1;
        const int t = t0 + s * dt;
        if (active) seq2[((size_t)t * BP + bp) * D2 + d * HID + j] = __float22half2_rn(h);
    }
}

// ---------------- FC epilogue on last timestep ----------------
__global__ void fc_kernel(const float* __restrict__ fc_w, const float* __restrict__ fc_b,
                          const float* __restrict__ omean, const float* __restrict__ ostd,
                          float* __restrict__ out) {
    int idx = blockIdx.x * blockDim.x + threadIdx.x;
    if (idx >= B_SZ * OUTD) return;
    int b = idx / OUTD, o = idx % OUTD;
    const __half2* lastp = g_sA2h + ((size_t)(T_LEN - 1) * BP + (b >> 1)) * D2;
    int par = b & 1;
    float acc = fc_b[o];
#pragma unroll
    for (int k = 0; k < D2; k++) {
        float2 v = __half22float2(lastp[k]);
        float hv = par ? v.y : v.x;
        acc += hv * fc_w[o * D2 + k];
    }
    out[idx] = acc * ostd[o] + omean[o];
}

// ---------------- launch ----------------
extern "C" void kernel_launch(void* const* d_in, const int* in_sizes, int n_in,
                              void* d_out, int out_size) {
    const float* x         = (const float*)d_in[0];
    const float* fmean     = (const float*)d_in[1];
    const float* fstd      = (const float*)d_in[2];
    const float* omean     = (const float*)d_in[3];
    const float* ostd      = (const float*)d_in[4];
    const float* w_ih_l0   = (const float*)d_in[5];
    const float* w_hh_l0   = (const float*)d_in[6];
    const float* b_ih_l0   = (const float*)d_in[7];
    const float* b_hh_l0   = (const float*)d_in[8];
    const float* w_ih_rest = (const float*)d_in[9];
    const float* w_hh_rest = (const float*)d_in[10];
    const float* b_ih_rest = (const float*)d_in[11];
    const float* b_hh_rest = (const float*)d_in[12];
    const float* fc_w      = (const float*)d_in[13];
    const float* fc_b      = (const float*)d_in[14];
    float* out             = (float*)d_out;

    dim3 xg_grid((unsigned)(M_PAIRS / 32), 2);   // 16384 x 2
    dim3 gru_grid(BP / 2, 2);

    // layer 0: x (fused norm) -> sA2
    xg_mma<FIN><<<xg_grid, 128>>>(0, w_ih_l0, b_ih_l0, x, fmean, fstd);
    gru_kernel<<<gru_grid, 64>>>(w_hh_l0, b_hh_l0, /*outsel=*/1);

    // layer 1: sA2 -> sB2
    xg_mma<D2><<<xg_grid, 128>>>(1, w_ih_rest, b_ih_rest, nullptr, nullptr, nullptr);
    gru_kernel<<<gru_grid, 64>>>(w_hh_rest, b_hh_rest, /*outsel=*/2);

    // layer 2: sB2 -> sA2
    xg_mma<D2><<<xg_grid, 128>>>(2, w_ih_rest + (size_t)2 * G3 * D2,
                                 b_ih_rest + 2 * G3, nullptr, nullptr, nullptr);
    gru_kernel<<<gru_grid, 64>>>(w_hh_rest + (size_t)2 * G3 * HID,
                                 b_hh_rest + 2 * G3, /*outsel=*/1);

    // FC epilogue
    {
        int threads = 256;
        int blocks = (B_SZ * OUTD + threads - 1) / threads;
        fc_kernel<<<blocks, threads>>>(fc_w, fc_b, omean, ostd, out);
    }
}